// round 1
// baseline (speedup 1.0000x reference)
#include <cuda_runtime.h>
#include <cstdint>

// Problem constants (fixed by the dataset)
#define IN_F   512
#define OUT_F  256
#define MAX_NODES 100000

// Scratch for support = X @ W  (100000 x 256 fp32 = 102.4 MB)
__device__ float g_support[(size_t)MAX_NODES * OUT_F];

// ---------------------------------------------------------------------------
// Kernel 1: tiled fp32 GEMM  C[M,256] = A[M,512] @ B[512,256]
// Block tile 64x64, K-tile 16, thread tile 4x4, 256 threads.
// ---------------------------------------------------------------------------
#define BM 64
#define BN 64
#define BK 16

__global__ __launch_bounds__(256) void gemm_kernel(
    const float* __restrict__ A, const float* __restrict__ B,
    float* __restrict__ C, int M)
{
    __shared__ float As[BK][BM];       // A stored transposed: As[k][m]
    __shared__ float Bs[BK][BN];

    const int tid = threadIdx.x;
    const int bn  = blockIdx.x;        // 0..3   (N / 64)
    const int bm  = blockIdx.y;        // M tiles
    const int row0 = bm * BM;

    // compute-thread mapping: 16x16 threads, each owns 4x4 outputs
    const int ty = tid >> 4;           // 0..15
    const int tx = tid & 15;           // 0..15

    // load mapping
    const int arow = tid >> 2;         // 0..63  (row within A tile)
    const int ak4  = tid & 3;          // 0..3   (float4 index along K)
    const int brow = tid >> 4;         // 0..15  (row within B tile = k)
    const int bc4  = tid & 15;         // 0..15  (float4 index along N)

    float acc[4][4] = {};

    for (int k0 = 0; k0 < IN_F; k0 += BK) {
        // --- load A tile (64 x 16), transpose into As[k][m] ---
        float4 av = make_float4(0.f, 0.f, 0.f, 0.f);
        const int gr = row0 + arow;
        if (gr < M)
            av = *reinterpret_cast<const float4*>(
                A + (size_t)gr * IN_F + k0 + ak4 * 4);
        As[ak4 * 4 + 0][arow] = av.x;
        As[ak4 * 4 + 1][arow] = av.y;
        As[ak4 * 4 + 2][arow] = av.z;
        As[ak4 * 4 + 3][arow] = av.w;

        // --- load B tile (16 x 64) ---
        float4 bv = *reinterpret_cast<const float4*>(
            B + (size_t)(k0 + brow) * OUT_F + bn * BN + bc4 * 4);
        *reinterpret_cast<float4*>(&Bs[brow][bc4 * 4]) = bv;

        __syncthreads();

        #pragma unroll
        for (int k = 0; k < BK; k++) {
            float a[4], b[4];
            #pragma unroll
            for (int i = 0; i < 4; i++) a[i] = As[k][ty * 4 + i];
            #pragma unroll
            for (int j = 0; j < 4; j++) b[j] = Bs[k][tx * 4 + j];
            #pragma unroll
            for (int i = 0; i < 4; i++)
                #pragma unroll
                for (int j = 0; j < 4; j++)
                    acc[i][j] += a[i] * b[j];
        }
        __syncthreads();
    }

    #pragma unroll
    for (int i = 0; i < 4; i++) {
        const int gr = row0 + ty * 4 + i;
        if (gr < M) {
            float4 v = make_float4(acc[i][0], acc[i][1], acc[i][2], acc[i][3]);
            *reinterpret_cast<float4*>(
                C + (size_t)gr * OUT_F + bn * BN + tx * 4) = v;
        }
    }
}

// ---------------------------------------------------------------------------
// Kernel 2: zero the output
// ---------------------------------------------------------------------------
__global__ void zero_kernel(float4* __restrict__ out, int n4)
{
    int i = blockIdx.x * blockDim.x + threadIdx.x;
    if (i < n4) out[i] = make_float4(0.f, 0.f, 0.f, 0.f);
}

// ---------------------------------------------------------------------------
// Kernel 3: SpMM scatter-add, one warp per edge.
// Each lane handles 8 of the 256 output features via two float4 chunks,
// accumulated into gmem with vector reductions (no return -> no scoreboard).
// ---------------------------------------------------------------------------
__device__ __forceinline__ void red_add_v4(float* p, float x, float y,
                                           float z, float w)
{
    asm volatile("red.global.add.v4.f32 [%0], {%1, %2, %3, %4};"
                 :: "l"(p), "f"(x), "f"(y), "f"(z), "f"(w) : "memory");
}

__global__ __launch_bounds__(256) void spmm_kernel(
    const int*   __restrict__ erow,
    const int*   __restrict__ ecol,
    const float* __restrict__ eval_,
    const float* __restrict__ sup,
    float*       __restrict__ out,
    int E)
{
    const int warp = (blockIdx.x * blockDim.x + threadIdx.x) >> 5;
    const int lane = threadIdx.x & 31;
    if (warp >= E) return;

    const int   r = erow[warp];
    const int   c = ecol[warp];
    const float v = eval_[warp];

    const float4* s = reinterpret_cast<const float4*>(sup + (size_t)c * OUT_F);
    float4 a = s[lane];        // features [4*lane, 4*lane+4)
    float4 b = s[lane + 32];   // features [128 + 4*lane, ...)

    float* o = out + (size_t)r * OUT_F;
    red_add_v4(o + 4 * lane,       a.x * v, a.y * v, a.z * v, a.w * v);
    red_add_v4(o + 128 + 4 * lane, b.x * v, b.y * v, b.z * v, b.w * v);
}

// ---------------------------------------------------------------------------
// Kernel 4: ReLU in place
// ---------------------------------------------------------------------------
__global__ void relu_kernel(float4* __restrict__ out, int n4)
{
    int i = blockIdx.x * blockDim.x + threadIdx.x;
    if (i < n4) {
        float4 v = out[i];
        v.x = fmaxf(v.x, 0.f);
        v.y = fmaxf(v.y, 0.f);
        v.z = fmaxf(v.z, 0.f);
        v.w = fmaxf(v.w, 0.f);
        out[i] = v;
    }
}

// ---------------------------------------------------------------------------
// launch
// inputs (metadata order): x [M*512] f32, weight [512*256] f32,
//                          edge_row [E] i32, edge_col [E] i32, edge_val [E] f32
// output: [M*256] f32
// ---------------------------------------------------------------------------
extern "C" void kernel_launch(void* const* d_in, const int* in_sizes, int n_in,
                              void* d_out, int out_size)
{
    const float* x      = (const float*)d_in[0];
    const float* weight = (const float*)d_in[1];
    const int*   erow   = (const int*)  d_in[2];
    const int*   ecol   = (const int*)  d_in[3];
    const float* eval_  = (const float*)d_in[4];
    float*       out    = (float*)d_out;

    const int M = in_sizes[0] / IN_F;      // 100000
    const int E = in_sizes[2];             // 3200000

    float* sup;
    cudaGetSymbolAddress((void**)&sup, g_support);

    // 1) support = x @ weight
    dim3 ggrid(OUT_F / BN, (M + BM - 1) / BM);
    gemm_kernel<<<ggrid, 256>>>(x, weight, sup, M);

    // 2) out = 0
    const int n4 = (M * OUT_F) / 4;
    zero_kernel<<<(n4 + 255) / 256, 256>>>((float4*)out, n4);

    // 3) scatter-add
    const int edges_per_block = 256 / 32;
    spmm_kernel<<<(E + edges_per_block - 1) / edges_per_block, 256>>>(
        erow, ecol, eval_, sup, out, E);

    // 4) relu
    relu_kernel<<<(n4 + 255) / 256, 256>>>((float4*)out, n4);
}

// round 4
// speedup vs baseline: 1.3111x; 1.3111x over previous
#include <cuda_runtime.h>
#include <cuda_bf16.h>
#include <cstdint>

#define IN_F   512
#define OUT_F  256
#define K2     1536          // [Ah | Al | Ah] concatenated K
#define MAX_NODES 100000

// Scratch (static device allocations; no cudaMalloc allowed)
__device__ float         g_support[(size_t)MAX_NODES * OUT_F];   // X @ W
__device__ __nv_bfloat16 g_a2[(size_t)MAX_NODES * K2];           // [m][1536]
__device__ __nv_bfloat16 g_w2[(size_t)OUT_F * K2];               // [n][1536] (W^T splits)

// ---------------------------------------------------------------------------
// small PTX helpers (all plain sm_80-era features -> compile for sm_100)
// ---------------------------------------------------------------------------
__device__ __forceinline__ uint32_t smem_u32(const void* p) {
    uint32_t a;
    asm("{ .reg .u64 t; cvta.to.shared.u64 t, %1; cvt.u32.u64 %0, t; }"
        : "=r"(a) : "l"(p));
    return a;
}
__device__ __forceinline__ void cp_async16(uint32_t sp, const void* gp, int sz) {
    asm volatile("cp.async.cg.shared.global [%0], [%1], 16, %2;"
                 :: "r"(sp), "l"(gp), "r"(sz) : "memory");
}
__device__ __forceinline__ void cp_commit() {
    asm volatile("cp.async.commit_group;" ::: "memory");
}
__device__ __forceinline__ void cp_wait1() {
    asm volatile("cp.async.wait_group 1;" ::: "memory");
}
__device__ __forceinline__ void cp_wait0() {
    asm volatile("cp.async.wait_group 0;" ::: "memory");
}
__device__ __forceinline__ void ldmatrix_x4(uint32_t* r, uint32_t addr) {
    asm volatile("ldmatrix.sync.aligned.m8n8.x4.shared.b16 {%0,%1,%2,%3}, [%4];"
                 : "=r"(r[0]), "=r"(r[1]), "=r"(r[2]), "=r"(r[3]) : "r"(addr));
}
__device__ __forceinline__ void mma_bf16(float* c, const uint32_t* a,
                                         const uint32_t* b) {
    asm volatile(
        "mma.sync.aligned.m16n8k16.row.col.f32.bf16.bf16.f32 "
        "{%0,%1,%2,%3}, {%4,%5,%6,%7}, {%8,%9}, {%0,%1,%2,%3};"
        : "+f"(c[0]), "+f"(c[1]), "+f"(c[2]), "+f"(c[3])
        : "r"(a[0]), "r"(a[1]), "r"(a[2]), "r"(a[3]), "r"(b[0]), "r"(b[1]));
}

// ---------------------------------------------------------------------------
// Prep 0: W [512,256] fp32 -> W2 [256][1536] bf16 rows = [Bh | Bh | Bl]
// ---------------------------------------------------------------------------
__global__ void wsplit_kernel(const float* __restrict__ w,
                              __nv_bfloat16* __restrict__ w2)
{
    int k = blockIdx.x;          // 0..511
    int n = threadIdx.x;         // 0..255
    float v = w[k * OUT_F + n];
    __nv_bfloat16 h = __float2bfloat16(v);
    __nv_bfloat16 l = __float2bfloat16(v - __bfloat162float(h));
    __nv_bfloat16* row = w2 + (size_t)n * K2;
    row[k]        = h;
    row[512 + k]  = h;
    row[1024 + k] = l;
}

// ---------------------------------------------------------------------------
// Prep 1: A [M,512] fp32 -> A2 [M][1536] bf16 rows = [Ah | Al | Ah]
// one thread = 8 floats (two float4 reads, three 16B writes)
// ---------------------------------------------------------------------------
__global__ void asplit_kernel(const float* __restrict__ A,
                              __nv_bfloat16* __restrict__ A2, int M)
{
    size_t i = (size_t)blockIdx.x * blockDim.x + threadIdx.x;
    if (i >= (size_t)M * (IN_F / 8)) return;
    int m  = (int)(i >> 6);          // 512/8 = 64 chunks per row
    int kq = (int)(i & 63);

    const float4* src = reinterpret_cast<const float4*>(
        A + (size_t)m * IN_F + kq * 8);
    float4 v0 = src[0], v1 = src[1];
    float f[8] = {v0.x, v0.y, v0.z, v0.w, v1.x, v1.y, v1.z, v1.w};

    unsigned short hs[8], ls[8];
    #pragma unroll
    for (int j = 0; j < 8; j++) {
        __nv_bfloat16 h = __float2bfloat16(f[j]);
        __nv_bfloat16 l = __float2bfloat16(f[j] - __bfloat162float(h));
        hs[j] = *reinterpret_cast<unsigned short*>(&h);
        ls[j] = *reinterpret_cast<unsigned short*>(&l);
    }
    uint4 hv = *reinterpret_cast<uint4*>(hs);
    uint4 lv = *reinterpret_cast<uint4*>(ls);

    __nv_bfloat16* row = A2 + (size_t)m * K2 + kq * 8;
    *reinterpret_cast<uint4*>(row)        = hv;
    *reinterpret_cast<uint4*>(row + 512)  = lv;
    *reinterpret_cast<uint4*>(row + 1024) = hv;
}

// ---------------------------------------------------------------------------
// GEMM: C[M,256] = A2[M,1536] @ W2^T   (bf16 HMMA, fp32 accum)
// Block tile 128x128, BK=32, 8 warps (4M x 2N), warp tile 32x64.
// Double-buffered cp.async; smem row stride 80B (conflict-free ldmatrix).
// ---------------------------------------------------------------------------
#define BM 128
#define BN 128
#define BK 32
#define NKT (K2 / BK)        // 48
#define ROW_B 80             // smem row stride bytes (32 bf16 + 8 pad)
#define STAGE (BM * ROW_B)   // 10240B per stage per operand

__global__ void __launch_bounds__(256) gemm_mma_kernel(
    const __nv_bfloat16* __restrict__ A2,
    const __nv_bfloat16* __restrict__ B2,
    float* __restrict__ C, int M)
{
    __shared__ __align__(16) unsigned char sm[4 * STAGE];

    const int tid  = threadIdx.x;
    const int wid  = tid >> 5;
    const int lane = tid & 31;
    const int row0 = blockIdx.y * BM;     // M offset
    const int n0   = blockIdx.x * BN;     // N offset (grid.x = 2, adjacent share A)

    const uint32_t smA = smem_u32(sm);
    const uint32_t smB = smA + 2 * STAGE;

    // loader mapping: 256 threads, 16B each, 2 rows-chunks per operand
    const int lrow = tid >> 2;            // 0..63
    const int lcol = tid & 3;             // 16B chunk within 64B row

    auto load_stage = [&](int kt, int s) {
        #pragma unroll
        for (int c = 0; c < 2; c++) {
            int r  = lrow + c * 64;
            int gr = row0 + r;
            int grc = gr < M ? gr : (M - 1);
            const __nv_bfloat16* gp = A2 + (size_t)grc * K2 + kt * BK + lcol * 8;
            cp_async16(smA + s * STAGE + r * ROW_B + lcol * 16, gp,
                       gr < M ? 16 : 0);
        }
        #pragma unroll
        for (int c = 0; c < 2; c++) {
            int r = lrow + c * 64;
            const __nv_bfloat16* gp = B2 + (size_t)(n0 + r) * K2 + kt * BK + lcol * 8;
            cp_async16(smB + s * STAGE + r * ROW_B + lcol * 16, gp, 16);
        }
    };

    const int m_base = (wid & 3) * 32;
    const int n_base = (wid >> 2) * 64;

    float acc[2][8][4] = {};

    load_stage(0, 0);
    cp_commit();

    for (int kt = 0; kt < NKT; kt++) {
        const int s = kt & 1;
        if (kt + 1 < NKT) {
            load_stage(kt + 1, s ^ 1);
            cp_commit();
            cp_wait1();
        } else {
            cp_wait0();
        }
        __syncthreads();

        #pragma unroll
        for (int ks = 0; ks < 2; ks++) {
            // A frags: 2 x m16k16
            uint32_t a[2][4];
            #pragma unroll
            for (int fm = 0; fm < 2; fm++) {
                uint32_t addr = smA + s * STAGE
                    + (m_base + fm * 16 + (lane & 15)) * ROW_B
                    + ks * 32 + ((lane >> 4) & 1) * 16;
                ldmatrix_x4(a[fm], addr);
            }
            // B frags: 8 x n8k16 via 4 ldmatrix.x4
            uint32_t b[8][2];
            #pragma unroll
            for (int fj = 0; fj < 4; fj++) {
                int nrow = n_base + fj * 16 + (lane & 7) + ((lane >> 4) & 1) * 8;
                uint32_t addr = smB + s * STAGE + nrow * ROW_B
                    + ks * 32 + ((lane >> 3) & 1) * 16;
                uint32_t r[4];
                ldmatrix_x4(r, addr);
                b[fj * 2 + 0][0] = r[0]; b[fj * 2 + 0][1] = r[1];
                b[fj * 2 + 1][0] = r[2]; b[fj * 2 + 1][1] = r[3];
            }
            #pragma unroll
            for (int fm = 0; fm < 2; fm++)
                #pragma unroll
                for (int fn = 0; fn < 8; fn++)
                    mma_bf16(acc[fm][fn], a[fm], b[fn]);
        }
        __syncthreads();
    }

    // epilogue: standard m16n8 C fragment mapping
    #pragma unroll
    for (int fm = 0; fm < 2; fm++) {
        const int r_lo = row0 + m_base + fm * 16 + (lane >> 2);
        const int r_hi = r_lo + 8;
        #pragma unroll
        for (int fn = 0; fn < 8; fn++) {
            const int col = n0 + n_base + fn * 8 + (lane & 3) * 2;
            if (r_lo < M)
                *reinterpret_cast<float2*>(C + (size_t)r_lo * OUT_F + col) =
                    make_float2(acc[fm][fn][0], acc[fm][fn][1]);
            if (r_hi < M)
                *reinterpret_cast<float2*>(C + (size_t)r_hi * OUT_F + col) =
                    make_float2(acc[fm][fn][2], acc[fm][fn][3]);
        }
    }
}

// ---------------------------------------------------------------------------
// zero output
// ---------------------------------------------------------------------------
__global__ void zero_kernel(float4* __restrict__ out, int n4)
{
    int i = blockIdx.x * blockDim.x + threadIdx.x;
    if (i < n4) out[i] = make_float4(0.f, 0.f, 0.f, 0.f);
}

// ---------------------------------------------------------------------------
// SpMM scatter-add: warp/edge, red.global.add.v4
// ---------------------------------------------------------------------------
__device__ __forceinline__ void red_add_v4(float* p, float x, float y,
                                           float z, float w)
{
    asm volatile("red.global.add.v4.f32 [%0], {%1, %2, %3, %4};"
                 :: "l"(p), "f"(x), "f"(y), "f"(z), "f"(w) : "memory");
}

__global__ __launch_bounds__(256) void spmm_kernel(
    const int*   __restrict__ erow,
    const int*   __restrict__ ecol,
    const float* __restrict__ eval_,
    const float* __restrict__ sup,
    float*       __restrict__ out,
    int E)
{
    const int warp = (blockIdx.x * blockDim.x + threadIdx.x) >> 5;
    const int lane = threadIdx.x & 31;
    if (warp >= E) return;

    const int   r = erow[warp];
    const int   c = ecol[warp];
    const float v = eval_[warp];

    const float4* s = reinterpret_cast<const float4*>(sup + (size_t)c * OUT_F);
    float4 a = s[lane];
    float4 b = s[lane + 32];

    float* o = out + (size_t)r * OUT_F;
    red_add_v4(o + 4 * lane,       a.x * v, a.y * v, a.z * v, a.w * v);
    red_add_v4(o + 128 + 4 * lane, b.x * v, b.y * v, b.z * v, b.w * v);
}

// ---------------------------------------------------------------------------
// ReLU in place
// ---------------------------------------------------------------------------
__global__ void relu_kernel(float4* __restrict__ out, int n4)
{
    int i = blockIdx.x * blockDim.x + threadIdx.x;
    if (i < n4) {
        float4 v = out[i];
        v.x = fmaxf(v.x, 0.f);
        v.y = fmaxf(v.y, 0.f);
        v.z = fmaxf(v.z, 0.f);
        v.w = fmaxf(v.w, 0.f);
        out[i] = v;
    }
}

// ---------------------------------------------------------------------------
extern "C" void kernel_launch(void* const* d_in, const int* in_sizes, int n_in,
                              void* d_out, int out_size)
{
    const float* x      = (const float*)d_in[0];
    const float* weight = (const float*)d_in[1];
    const int*   erow   = (const int*)  d_in[2];
    const int*   ecol   = (const int*)  d_in[3];
    const float* eval_  = (const float*)d_in[4];
    float*       out    = (float*)d_out;

    const int M = in_sizes[0] / IN_F;      // 100000
    const int E = in_sizes[2];             // 3200000

    float* sup;          cudaGetSymbolAddress((void**)&sup, g_support);
    __nv_bfloat16* a2;   cudaGetSymbolAddress((void**)&a2, g_a2);
    __nv_bfloat16* w2;   cudaGetSymbolAddress((void**)&w2, g_w2);

    // 0) weight transpose + split  /  A split
    wsplit_kernel<<<IN_F, OUT_F>>>(weight, w2);
    {
        size_t total = (size_t)M * (IN_F / 8);
        asplit_kernel<<<(unsigned)((total + 255) / 256), 256>>>(x, a2, M);
    }

    // 1) support = x @ weight  (bf16 HMMA, K-concat split)
    {
        dim3 grid(OUT_F / BN, (M + BM - 1) / BM);
        gemm_mma_kernel<<<grid, 256>>>(a2, w2, sup, M);
    }

    // 2) out = 0
    const int n4 = (M * OUT_F) / 4;
    zero_kernel<<<(n4 + 255) / 256, 256>>>((float4*)out, n4);

    // 3) scatter-add
    spmm_kernel<<<(E + 7) / 8, 256>>>(erow, ecol, eval_, sup, out, E);

    // 4) relu
    relu_kernel<<<(n4 + 255) / 256, 256>>>((float4*)out, n4);
}

// round 5
// speedup vs baseline: 2.3649x; 1.8038x over previous
#include <cuda_runtime.h>
#include <cuda_bf16.h>
#include <cstdint>

#define IN_F   512
#define OUT_F  256
#define K2     1536          // [Ah | Al | Ah] concatenated K
#define MAX_NODES 100000
#define MAX_EDGES 3200000
#define CHUNK    1024
#define NCHUNK   ((MAX_NODES + CHUNK - 1) / CHUNK)   // 98

// Scratch (static device allocations; no cudaMalloc allowed)
__device__ float         g_support[(size_t)MAX_NODES * OUT_F];   // X @ W
__device__ __nv_bfloat16 g_a2[(size_t)MAX_NODES * K2];           // [m][1536]
__device__ __nv_bfloat16 g_w2[(size_t)OUT_F * K2];               // [n][1536]
__device__ int           g_cnt[MAX_NODES];                       // row degree
__device__ int           g_rowptr[MAX_NODES + 1];                // CSR offsets
__device__ int           g_woff[MAX_NODES];                      // scatter cursors
__device__ int           g_bsum[NCHUNK];                         // chunk sums
__device__ int           g_boff[NCHUNK];                         // chunk bases
__device__ int2          g_epack[MAX_EDGES];                     // (col, val) CSR

// ---------------------------------------------------------------------------
// PTX helpers
// ---------------------------------------------------------------------------
__device__ __forceinline__ uint32_t smem_u32(const void* p) {
    uint32_t a;
    asm("{ .reg .u64 t; cvta.to.shared.u64 t, %1; cvt.u32.u64 %0, t; }"
        : "=r"(a) : "l"(p));
    return a;
}
__device__ __forceinline__ void cp_async16(uint32_t sp, const void* gp, int sz) {
    asm volatile("cp.async.cg.shared.global [%0], [%1], 16, %2;"
                 :: "r"(sp), "l"(gp), "r"(sz) : "memory");
}
__device__ __forceinline__ void cp_commit() {
    asm volatile("cp.async.commit_group;" ::: "memory");
}
__device__ __forceinline__ void cp_wait1() {
    asm volatile("cp.async.wait_group 1;" ::: "memory");
}
__device__ __forceinline__ void cp_wait0() {
    asm volatile("cp.async.wait_group 0;" ::: "memory");
}
__device__ __forceinline__ void ldmatrix_x4(uint32_t* r, uint32_t addr) {
    asm volatile("ldmatrix.sync.aligned.m8n8.x4.shared.b16 {%0,%1,%2,%3}, [%4];"
                 : "=r"(r[0]), "=r"(r[1]), "=r"(r[2]), "=r"(r[3]) : "r"(addr));
}
__device__ __forceinline__ void mma_bf16(float* c, const uint32_t* a,
                                         const uint32_t* b) {
    asm volatile(
        "mma.sync.aligned.m16n8k16.row.col.f32.bf16.bf16.f32 "
        "{%0,%1,%2,%3}, {%4,%5,%6,%7}, {%8,%9}, {%0,%1,%2,%3};"
        : "+f"(c[0]), "+f"(c[1]), "+f"(c[2]), "+f"(c[3])
        : "r"(a[0]), "r"(a[1]), "r"(a[2]), "r"(a[3]), "r"(b[0]), "r"(b[1]));
}

// ---------------------------------------------------------------------------
// Prep 0: W [512,256] fp32 -> W2 [256][1536] bf16 rows = [Bh | Bh | Bl]
// ---------------------------------------------------------------------------
__global__ void wsplit_kernel(const float* __restrict__ w,
                              __nv_bfloat16* __restrict__ w2)
{
    int k = blockIdx.x;          // 0..511
    int n = threadIdx.x;         // 0..255
    float v = w[k * OUT_F + n];
    __nv_bfloat16 h = __float2bfloat16(v);
    __nv_bfloat16 l = __float2bfloat16(v - __bfloat162float(h));
    __nv_bfloat16* row = w2 + (size_t)n * K2;
    row[k]        = h;
    row[512 + k]  = h;
    row[1024 + k] = l;
}

// ---------------------------------------------------------------------------
// Prep 1: A [M,512] fp32 -> A2 [M][1536] bf16 rows = [Ah | Al | Ah]
// ---------------------------------------------------------------------------
__global__ void asplit_kernel(const float* __restrict__ A,
                              __nv_bfloat16* __restrict__ A2, int M)
{
    size_t i = (size_t)blockIdx.x * blockDim.x + threadIdx.x;
    if (i >= (size_t)M * (IN_F / 8)) return;
    int m  = (int)(i >> 6);
    int kq = (int)(i & 63);

    const float4* src = reinterpret_cast<const float4*>(
        A + (size_t)m * IN_F + kq * 8);
    float4 v0 = src[0], v1 = src[1];
    float f[8] = {v0.x, v0.y, v0.z, v0.w, v1.x, v1.y, v1.z, v1.w};

    unsigned short hs[8], ls[8];
    #pragma unroll
    for (int j = 0; j < 8; j++) {
        __nv_bfloat16 h = __float2bfloat16(f[j]);
        __nv_bfloat16 l = __float2bfloat16(f[j] - __bfloat162float(h));
        hs[j] = *reinterpret_cast<unsigned short*>(&h);
        ls[j] = *reinterpret_cast<unsigned short*>(&l);
    }
    uint4 hv = *reinterpret_cast<uint4*>(hs);
    uint4 lv = *reinterpret_cast<uint4*>(ls);

    __nv_bfloat16* row = A2 + (size_t)m * K2 + kq * 8;
    *reinterpret_cast<uint4*>(row)        = hv;
    *reinterpret_cast<uint4*>(row + 512)  = lv;
    *reinterpret_cast<uint4*>(row + 1024) = hv;
}

// ---------------------------------------------------------------------------
// GEMM: C[M,256] = A2[M,1536] @ W2^T  (bf16 HMMA, fp32 accum) — unchanged R4
// ---------------------------------------------------------------------------
#define BM 128
#define BN 128
#define BK 32
#define NKT (K2 / BK)        // 48
#define ROW_B 80
#define STAGE (BM * ROW_B)

__global__ void __launch_bounds__(256) gemm_mma_kernel(
    const __nv_bfloat16* __restrict__ A2,
    const __nv_bfloat16* __restrict__ B2,
    float* __restrict__ C, int M)
{
    __shared__ __align__(16) unsigned char sm[4 * STAGE];

    const int tid  = threadIdx.x;
    const int wid  = tid >> 5;
    const int lane = tid & 31;
    const int row0 = blockIdx.y * BM;
    const int n0   = blockIdx.x * BN;

    const uint32_t smA = smem_u32(sm);
    const uint32_t smB = smA + 2 * STAGE;

    const int lrow = tid >> 2;
    const int lcol = tid & 3;

    auto load_stage = [&](int kt, int s) {
        #pragma unroll
        for (int c = 0; c < 2; c++) {
            int r  = lrow + c * 64;
            int gr = row0 + r;
            int grc = gr < M ? gr : (M - 1);
            const __nv_bfloat16* gp = A2 + (size_t)grc * K2 + kt * BK + lcol * 8;
            cp_async16(smA + s * STAGE + r * ROW_B + lcol * 16, gp,
                       gr < M ? 16 : 0);
        }
        #pragma unroll
        for (int c = 0; c < 2; c++) {
            int r = lrow + c * 64;
            const __nv_bfloat16* gp = B2 + (size_t)(n0 + r) * K2 + kt * BK + lcol * 8;
            cp_async16(smB + s * STAGE + r * ROW_B + lcol * 16, gp, 16);
        }
    };

    const int m_base = (wid & 3) * 32;
    const int n_base = (wid >> 2) * 64;

    float acc[2][8][4] = {};

    load_stage(0, 0);
    cp_commit();

    for (int kt = 0; kt < NKT; kt++) {
        const int s = kt & 1;
        if (kt + 1 < NKT) {
            load_stage(kt + 1, s ^ 1);
            cp_commit();
            cp_wait1();
        } else {
            cp_wait0();
        }
        __syncthreads();

        #pragma unroll
        for (int ks = 0; ks < 2; ks++) {
            uint32_t a[2][4];
            #pragma unroll
            for (int fm = 0; fm < 2; fm++) {
                uint32_t addr = smA + s * STAGE
                    + (m_base + fm * 16 + (lane & 15)) * ROW_B
                    + ks * 32 + ((lane >> 4) & 1) * 16;
                ldmatrix_x4(a[fm], addr);
            }
            uint32_t b[8][2];
            #pragma unroll
            for (int fj = 0; fj < 4; fj++) {
                int nrow = n_base + fj * 16 + (lane & 7) + ((lane >> 4) & 1) * 8;
                uint32_t addr = smB + s * STAGE + nrow * ROW_B
                    + ks * 32 + ((lane >> 3) & 1) * 16;
                uint32_t r[4];
                ldmatrix_x4(r, addr);
                b[fj * 2 + 0][0] = r[0]; b[fj * 2 + 0][1] = r[1];
                b[fj * 2 + 1][0] = r[2]; b[fj * 2 + 1][1] = r[3];
            }
            #pragma unroll
            for (int fm = 0; fm < 2; fm++)
                #pragma unroll
                for (int fn = 0; fn < 8; fn++)
                    mma_bf16(acc[fm][fn], a[fm], b[fn]);
        }
        __syncthreads();
    }

    #pragma unroll
    for (int fm = 0; fm < 2; fm++) {
        const int r_lo = row0 + m_base + fm * 16 + (lane >> 2);
        const int r_hi = r_lo + 8;
        #pragma unroll
        for (int fn = 0; fn < 8; fn++) {
            const int col = n0 + n_base + fn * 8 + (lane & 3) * 2;
            if (r_lo < M)
                *reinterpret_cast<float2*>(C + (size_t)r_lo * OUT_F + col) =
                    make_float2(acc[fm][fn][0], acc[fm][fn][1]);
            if (r_hi < M)
                *reinterpret_cast<float2*>(C + (size_t)r_hi * OUT_F + col) =
                    make_float2(acc[fm][fn][2], acc[fm][fn][3]);
        }
    }
}

// ---------------------------------------------------------------------------
// CSR build: histogram -> scan -> scatter
// ---------------------------------------------------------------------------
__global__ void zero_cnt_kernel(int* __restrict__ cnt, int N)
{
    int i = blockIdx.x * blockDim.x + threadIdx.x;
    if (i < N) cnt[i] = 0;
}

__global__ void hist_kernel(const int* __restrict__ erow,
                            int* __restrict__ cnt, int E)
{
    int i = (blockIdx.x * blockDim.x + threadIdx.x) * 4;
    if (i >= E) return;
    int4 r = *reinterpret_cast<const int4*>(erow + i);
    atomicAdd(&cnt[r.x], 1);
    atomicAdd(&cnt[r.y], 1);
    atomicAdd(&cnt[r.z], 1);
    atomicAdd(&cnt[r.w], 1);
}

// chunk sums: block b reduces cnt[b*1024 .. b*1024+1023]
__global__ void chunk_sum_kernel(const int* __restrict__ cnt,
                                 int* __restrict__ bsum, int N)
{
    __shared__ int ssum[256];
    int b = blockIdx.x, t = threadIdx.x;
    int base = b * CHUNK + t * 4;
    int s = 0;
    #pragma unroll
    for (int k = 0; k < 4; k++) {
        int i = base + k;
        if (i < N) s += cnt[i];
    }
    ssum[t] = s; __syncthreads();
    for (int off = 128; off > 0; off >>= 1) {
        if (t < off) ssum[t] += ssum[t + off];
        __syncthreads();
    }
    if (t == 0) bsum[b] = ssum[0];
}

// exclusive scan of NCHUNK (<=128) chunk sums; also rowptr[N] = E
__global__ void scan_bsum_kernel(const int* __restrict__ bsum,
                                 int* __restrict__ boff,
                                 int* __restrict__ rowptr, int N, int E)
{
    __shared__ int ss[128];
    int t = threadIdx.x;
    int v = (t < NCHUNK) ? bsum[t] : 0;
    ss[t] = v; __syncthreads();
    #pragma unroll
    for (int off = 1; off < 128; off <<= 1) {
        int u = (t >= off) ? ss[t - off] : 0;
        __syncthreads();
        ss[t] += u;
        __syncthreads();
    }
    if (t < NCHUNK) boff[t] = ss[t] - v;   // exclusive
    if (t == 0) rowptr[N] = E;
}

// per-chunk exclusive scan + base; writes rowptr and woff
__global__ void scan_chunk_kernel(const int* __restrict__ cnt,
                                  const int* __restrict__ boff,
                                  int* __restrict__ rowptr,
                                  int* __restrict__ woff, int N)
{
    __shared__ int ss[256];
    int b = blockIdx.x, t = threadIdx.x;
    int base = b * CHUNK + t * 4;
    int c[4];
    int tot = 0;
    #pragma unroll
    for (int k = 0; k < 4; k++) {
        int i = base + k;
        c[k] = (i < N) ? cnt[i] : 0;
        tot += c[k];
    }
    ss[t] = tot; __syncthreads();
    #pragma unroll
    for (int off = 1; off < 256; off <<= 1) {
        int u = (t >= off) ? ss[t - off] : 0;
        __syncthreads();
        ss[t] += u;
        __syncthreads();
    }
    int run = boff[b] + ss[t] - tot;       // exclusive thread base
    #pragma unroll
    for (int k = 0; k < 4; k++) {
        int i = base + k;
        if (i < N) { rowptr[i] = run; woff[i] = run; }
        run += c[k];
    }
}

__global__ void scatter_kernel(const int*   __restrict__ erow,
                               const int*   __restrict__ ecol,
                               const float* __restrict__ eval_,
                               int*  __restrict__ woff,
                               int2* __restrict__ epack, int E)
{
    int e = blockIdx.x * blockDim.x + threadIdx.x;
    if (e >= E) return;
    int r = erow[e];
    int pos = atomicAdd(&woff[r], 1);
    epack[pos] = make_int2(ecol[e], __float_as_int(eval_[e]));
}

// ---------------------------------------------------------------------------
// Gather: warp per (row, 128-feature half). Fused zero-init + ReLU + store.
// ---------------------------------------------------------------------------
__global__ void __launch_bounds__(256) gather_kernel(
    const int*   __restrict__ rowptr,
    const int2*  __restrict__ epack,
    const float* __restrict__ sup,
    float*       __restrict__ out, int N)
{
    const int gw   = blockIdx.x * 8 + (threadIdx.x >> 5);
    const int lane = threadIdx.x & 31;
    const int row  = gw >> 1;
    const int half = gw & 1;
    if (row >= N) return;

    const int beg = rowptr[row];
    const int end = rowptr[row + 1];

    const float* supb = sup + (size_t)half * 128 + lane * 4;
    float4 acc = make_float4(0.f, 0.f, 0.f, 0.f);

    for (int base = beg; base < end; base += 32) {
        int i = base + lane;
        int2 ev = (i < end) ? epack[i] : make_int2(0, 0);
        int cntj = min(32, end - base);
        if (cntj == 32) {
            #pragma unroll 8
            for (int j = 0; j < 32; j++) {
                int   c = __shfl_sync(0xFFFFFFFFu, ev.x, j);
                float v = __int_as_float(__shfl_sync(0xFFFFFFFFu, ev.y, j));
                float4 s = *reinterpret_cast<const float4*>(
                    supb + (size_t)c * OUT_F);
                acc.x = fmaf(s.x, v, acc.x);
                acc.y = fmaf(s.y, v, acc.y);
                acc.z = fmaf(s.z, v, acc.z);
                acc.w = fmaf(s.w, v, acc.w);
            }
        } else {
            for (int j = 0; j < cntj; j++) {
                int   c = __shfl_sync(0xFFFFFFFFu, ev.x, j);
                float v = __int_as_float(__shfl_sync(0xFFFFFFFFu, ev.y, j));
                float4 s = *reinterpret_cast<const float4*>(
                    supb + (size_t)c * OUT_F);
                acc.x = fmaf(s.x, v, acc.x);
                acc.y = fmaf(s.y, v, acc.y);
                acc.z = fmaf(s.z, v, acc.z);
                acc.w = fmaf(s.w, v, acc.w);
            }
        }
    }

    acc.x = fmaxf(acc.x, 0.f);
    acc.y = fmaxf(acc.y, 0.f);
    acc.z = fmaxf(acc.z, 0.f);
    acc.w = fmaxf(acc.w, 0.f);
    *reinterpret_cast<float4*>(
        out + (size_t)row * OUT_F + half * 128 + lane * 4) = acc;
}

// ---------------------------------------------------------------------------
extern "C" void kernel_launch(void* const* d_in, const int* in_sizes, int n_in,
                              void* d_out, int out_size)
{
    const float* x      = (const float*)d_in[0];
    const float* weight = (const float*)d_in[1];
    const int*   erow   = (const int*)  d_in[2];
    const int*   ecol   = (const int*)  d_in[3];
    const float* eval_  = (const float*)d_in[4];
    float*       out    = (float*)d_out;

    const int M = in_sizes[0] / IN_F;      // 100000
    const int E = in_sizes[2];             // 3200000

    float* sup;          cudaGetSymbolAddress((void**)&sup, g_support);
    __nv_bfloat16* a2;   cudaGetSymbolAddress((void**)&a2, g_a2);
    __nv_bfloat16* w2;   cudaGetSymbolAddress((void**)&w2, g_w2);
    int*  cnt;           cudaGetSymbolAddress((void**)&cnt, g_cnt);
    int*  rowptr;        cudaGetSymbolAddress((void**)&rowptr, g_rowptr);
    int*  woff;          cudaGetSymbolAddress((void**)&woff, g_woff);
    int*  bsum;          cudaGetSymbolAddress((void**)&bsum, g_bsum);
    int*  boff;          cudaGetSymbolAddress((void**)&boff, g_boff);
    int2* epack;         cudaGetSymbolAddress((void**)&epack, g_epack);

    // ---- CSR build (overlaps conceptually with GEMM stream order) ----
    zero_cnt_kernel<<<(M + 255) / 256, 256>>>(cnt, M);
    hist_kernel<<<(E / 4 + 255) / 256, 256>>>(erow, cnt, E);
    chunk_sum_kernel<<<NCHUNK, 256>>>(cnt, bsum, M);
    scan_bsum_kernel<<<1, 128>>>(bsum, boff, rowptr, M, E);
    scan_chunk_kernel<<<NCHUNK, 256>>>(cnt, boff, rowptr, woff, M);
    scatter_kernel<<<(E + 255) / 256, 256>>>(erow, ecol, eval_, woff, epack, E);

    // ---- dense path ----
    wsplit_kernel<<<IN_F, OUT_F>>>(weight, w2);
    {
        size_t total = (size_t)M * (IN_F / 8);
        asplit_kernel<<<(unsigned)((total + 255) / 256), 256>>>(x, a2, M);
    }
    {
        dim3 grid(OUT_F / BN, (M + BM - 1) / BM);
        gemm_mma_kernel<<<grid, 256>>>(a2, w2, sup, M);
    }

    // ---- gather (fused zero + relu) ----
    gather_kernel<<<(M * 2 + 7) / 8, 256>>>(rowptr, epack, sup, out, M);
}